// round 2
// baseline (speedup 1.0000x reference)
#include <cuda_runtime.h>
#include <math.h>

#define BB 8
#define CC 256
#define HH 96
#define WW 128
#define HWSZ (HH*WW)
#define RD 4
#define ND 9           // 2*RD+1
#define TILE_H 8
#define TILE_W 32
#define NGROUP 8       // groups of 4 pixels along w
#define NTHREADS (NGROUP*TILE_H*ND)   // 576
#define CHUNK 8        // channels per smem stage

// Per-pixel inverse L2 norms (scratch; __device__ globals, no allocation)
__device__ float g_inv_fr[BB*HWSZ];
__device__ float g_inv_fq[BB*HWSZ];

__global__ void norm_kernel(const float* __restrict__ x, float* __restrict__ inv) {
    int p = blockIdx.x * blockDim.x + threadIdx.x;
    if (p >= BB*HWSZ) return;
    int b = p / HWSZ, r = p % HWSZ;
    const float* ptr = x + (size_t)b * CC * HWSZ + r;
    float s = 0.f;
    #pragma unroll 8
    for (int c = 0; c < CC; ++c) {
        float v = ptr[(size_t)c * HWSZ];
        s = fmaf(v, v, s);
    }
    float n = sqrtf(s);
    inv[p] = 1.0f / fmaxf(n, 1e-12f);
}

__global__ __launch_bounds__(NTHREADS, 1)
void corr_kernel(const float* __restrict__ fr, const float* __restrict__ fq,
                 float* __restrict__ out) {
    // fq tile with 4-halo on each side: 16 rows x 40 cols per channel
    __shared__ float s_fq[CHUNK][TILE_H + 2*RD][TILE_W + 2*RD];  // [8][16][40]
    __shared__ float s_fr[CHUNK][TILE_H][TILE_W];                // [8][8][32]

    const int b  = blockIdx.z;
    const int h0 = blockIdx.y * TILE_H;
    const int w0 = blockIdx.x * TILE_W;
    const int tid = threadIdx.x;
    const int g  = tid & 7;          // pixel group (4 px each)
    const int ty = (tid >> 3) & 7;   // tile row
    const int dy = tid >> 6;         // displacement row 0..8

    float acc[36];
    #pragma unroll
    for (int i = 0; i < 36; ++i) acc[i] = 0.f;

    const float* frb = fr + (size_t)b * CC * HWSZ;
    const float* fqb = fq + (size_t)b * CC * HWSZ;

    const int FQ_ELEMS = CHUNK * (TILE_H + 2*RD) * (TILE_W + 2*RD); // 5120
    const int FR_ELEMS = CHUNK * TILE_H * TILE_W;                   // 2048

    for (int c0 = 0; c0 < CC; c0 += CHUNK) {
        // stage fq tile (with zero halo)
        for (int idx = tid; idx < FQ_ELEMS; idx += NTHREADS) {
            int ch  = idx / 640;
            int rem = idx - ch * 640;
            int row = rem / 40;
            int col = rem - row * 40;
            int hg = h0 + row - RD;
            int wg = w0 + col - RD;
            float v = 0.f;
            if (hg >= 0 && hg < HH && wg >= 0 && wg < WW)
                v = fqb[(size_t)(c0 + ch) * HWSZ + hg * WW + wg];
            ((float*)s_fq)[idx] = v;
        }
        // stage fr tile
        for (int idx = tid; idx < FR_ELEMS; idx += NTHREADS) {
            int ch  = idx >> 8;
            int rem = idx & 255;
            int row = rem >> 5;
            int col = rem & 31;
            ((float*)s_fr)[idx] = frb[(size_t)(c0 + ch) * HWSZ + (h0 + row) * WW + (w0 + col)];
        }
        __syncthreads();

        #pragma unroll
        for (int ch = 0; ch < CHUNK; ++ch) {
            float4 f4 = *(const float4*)&s_fr[ch][ty][4*g];
            float fv[4] = {f4.x, f4.y, f4.z, f4.w};
            const float* rp = &s_fq[ch][ty + dy][4*g];
            float4 q0 = *(const float4*)(rp);
            float4 q1 = *(const float4*)(rp + 4);
            float4 q2 = *(const float4*)(rp + 8);
            float q[12] = {q0.x,q0.y,q0.z,q0.w, q1.x,q1.y,q1.z,q1.w, q2.x,q2.y,q2.z,q2.w};
            #pragma unroll
            for (int i = 0; i < 4; ++i) {
                #pragma unroll
                for (int dx = 0; dx < ND; ++dx) {
                    acc[i*ND + dx] = fmaf(fv[i], q[i + dx], acc[i*ND + dx]);
                }
            }
        }
        __syncthreads();
    }

    // epilogue: apply norms, write 9 float4 stores
    const int h = h0 + ty;
    const int w_base = w0 + 4*g;

    float invfr[4];
    #pragma unroll
    for (int i = 0; i < 4; ++i)
        invfr[i] = g_inv_fr[b*HWSZ + h*WW + w_base + i];

    const int hq = h + dy - RD;
    const bool vr = (hq >= 0 && hq < HH);
    float invq[12];
    #pragma unroll
    for (int j = 0; j < 12; ++j) {
        int wq = w_base + j - RD;
        invq[j] = (vr && wq >= 0 && wq < WW) ? g_inv_fq[b*HWSZ + hq*WW + wq] : 0.f;
    }

    const float scale = 1.0f / (float)CC;
    #pragma unroll
    for (int dx = 0; dx < ND; ++dx) {
        float4 o;
        o.x = acc[0*ND + dx] * invfr[0] * invq[0 + dx] * scale;
        o.y = acc[1*ND + dx] * invfr[1] * invq[1 + dx] * scale;
        o.z = acc[2*ND + dx] * invfr[2] * invq[2 + dx] * scale;
        o.w = acc[3*ND + dx] * invfr[3] * invq[3 + dx] * scale;
        size_t off = (((size_t)b * (ND*ND) + (size_t)(dy*ND + dx)) * HH + h) * WW + w_base;
        *(float4*)&out[off] = o;
    }
}

extern "C" void kernel_launch(void* const* d_in, const int* in_sizes, int n_in,
                              void* d_out, int out_size) {
    const float* fr = (const float*)d_in[0];
    const float* fq = (const float*)d_in[1];
    float* out = (float*)d_out;
    (void)in_sizes; (void)n_in; (void)out_size;

    float* d_inv_fr;
    float* d_inv_fq;
    cudaGetSymbolAddress((void**)&d_inv_fr, g_inv_fr);
    cudaGetSymbolAddress((void**)&d_inv_fq, g_inv_fq);

    {
        int total = BB * HWSZ;
        int threads = 256;
        int blocks = (total + threads - 1) / threads;
        norm_kernel<<<blocks, threads>>>(fr, d_inv_fr);
        norm_kernel<<<blocks, threads>>>(fq, d_inv_fq);
    }
    {
        dim3 grid(WW / TILE_W, HH / TILE_H, BB);   // (4, 12, 8)
        corr_kernel<<<grid, NTHREADS>>>(fr, fq, out);
    }
}

// round 4
// speedup vs baseline: 1.7693x; 1.7693x over previous
#include <cuda_runtime.h>
#include <cstdint>
#include <math.h>

#define BB 8
#define CC 256
#define HH 96
#define WW 128
#define HWSZ (HH*WW)
#define RD 4
#define ND 9           // 2*RD+1
#define TILE_H 8
#define TILE_W 32
#define NGROUP 8       // groups of 4 pixels along w
#define NTHREADS (NGROUP*TILE_H*ND)   // 576
#define CHUNK 8        // channels per smem stage
#define NCHUNK (CC/CHUNK)             // 32

// dynamic smem layout (floats):
//   s_fq : [2][CHUNK][16][40]  = 10240
//   s_fr : [2][CHUNK][8][32]   =  4096
//   s_frn: [8][32]             =   256   (inverse norms, fr tile)
//   s_fqn: [16][40]            =   640   (inverse norms, fq halo tile)
#define FQ_F   10240
#define FR_F    4096
#define SMEM_FLOATS (FQ_F + FR_F + 256 + 640)
#define SMEM_BYTES  (SMEM_FLOATS * 4)

#define FQ_CHUNKS 1280   // CHUNK*16*10  16B-chunks per stage
#define FR_CHUNKS  512   // CHUNK*8*8
#define TOT_CHUNKS (FQ_CHUNKS + FR_CHUNKS)  // 1792

__device__ __forceinline__ void cpasync16(float* dst, const float* src) {
    unsigned int sa = (unsigned int)__cvta_generic_to_shared(dst);
    asm volatile("cp.async.cg.shared.global [%0], [%1], 16;\n" :: "r"(sa), "l"(src));
}
__device__ __forceinline__ void sts_zero16(float* dst) {
    unsigned int sa = (unsigned int)__cvta_generic_to_shared(dst);
    asm volatile("st.shared.v4.b32 [%0], {%1,%1,%1,%1};\n" :: "r"(sa), "r"(0u));
}

__device__ __forceinline__ void stage(const float* __restrict__ frb,
                                      const float* __restrict__ fqb,
                                      float* __restrict__ s_fq,
                                      float* __restrict__ s_fr,
                                      int c0, int buf, int h0, int w0, int tid)
{
    #pragma unroll
    for (int it = 0; it < 4; ++it) {
        int idx = tid + it * NTHREADS;
        if (idx < TOT_CHUNKS) {
            if (idx < FQ_CHUNKS) {
                int ch  = idx / 160;
                int rem = idx - ch * 160;
                int row = rem / 10;
                int c16 = rem - row * 10;
                int hg = h0 + row - RD;
                int wg = w0 + c16 * 4 - RD;
                float* dst = s_fq + ((buf * CHUNK + ch) * 16 + row) * 40 + c16 * 4;
                if (hg >= 0 && hg < HH && wg >= 0 && wg <= WW - 4) {
                    cpasync16(dst, fqb + (size_t)(c0 + ch) * HWSZ + hg * WW + wg);
                } else {
                    sts_zero16(dst);
                }
            } else {
                int j   = idx - FQ_CHUNKS;
                int ch  = j >> 6;
                int rem = j & 63;
                int row = rem >> 3;
                int c16 = rem & 7;
                float* dst = s_fr + ((buf * CHUNK + ch) * 8 + row) * 32 + c16 * 4;
                cpasync16(dst, frb + (size_t)(c0 + ch) * HWSZ + (h0 + row) * WW + (w0 + c16 * 4));
            }
        }
    }
    asm volatile("cp.async.commit_group;\n");
}

__global__ __launch_bounds__(NTHREADS, 1)
void corr_kernel(const float* __restrict__ fr, const float* __restrict__ fq,
                 float* __restrict__ out) {
    extern __shared__ float sm[];
    float* s_fq  = sm;
    float* s_fr  = sm + FQ_F;
    float* s_frn = sm + FQ_F + FR_F;
    float* s_fqn = s_frn + 256;

    const int b  = blockIdx.z;
    const int h0 = blockIdx.y * TILE_H;
    const int w0 = blockIdx.x * TILE_W;
    const int tid = threadIdx.x;
    const int g  = tid & 7;          // pixel group (4 px each)
    const int ty = (tid >> 3) & 7;   // tile row
    const int dy = tid >> 6;         // displacement row 0..8

    // fq-norm coverage: pos0 for all threads, pos1 for tid<64 (640 = 16x40 halo positions)
    const int r0 = tid / 40,          c0p = tid - r0 * 40;
    const int p1 = tid + NTHREADS;
    const int r1 = p1 / 40,           c1p = p1 - r1 * 40;

    float acc[36];
    #pragma unroll
    for (int i = 0; i < 36; ++i) acc[i] = 0.f;
    float frs0 = 0.f, frs1 = 0.f, frs2 = 0.f, frs3 = 0.f;
    float fqs0 = 0.f, fqs1 = 0.f;

    const float* frb = fr + (size_t)b * CC * HWSZ;
    const float* fqb = fq + (size_t)b * CC * HWSZ;

    stage(frb, fqb, s_fq, s_fr, 0, 0, h0, w0, tid);

    for (int k = 0; k < NCHUNK; ++k) {
        if (k + 1 < NCHUNK) {
            stage(frb, fqb, s_fq, s_fr, (k + 1) * CHUNK, (k + 1) & 1, h0, w0, tid);
            asm volatile("cp.async.wait_group 1;\n");
        } else {
            asm volatile("cp.async.wait_group 0;\n");
        }
        __syncthreads();

        const int buf = k & 1;
        #pragma unroll
        for (int ch = 0; ch < CHUNK; ++ch) {
            const float* fqc = s_fq + (buf * CHUNK + ch) * 16 * 40;
            const float* frc = s_fr + (buf * CHUNK + ch) * 8 * 32;

            float4 f4 = *(const float4*)(frc + ty * 32 + 4 * g);
            const float* rp = fqc + (ty + dy) * 40 + 4 * g;
            float4 q0 = *(const float4*)(rp);
            float4 q1 = *(const float4*)(rp + 4);
            float4 q2 = *(const float4*)(rp + 8);

            // fused norm accumulation
            float qv = fqc[r0 * 40 + c0p];
            fqs0 = fmaf(qv, qv, fqs0);
            if (tid < 64) {
                float qv1 = fqc[r1 * 40 + c1p];
                fqs1 = fmaf(qv1, qv1, fqs1);
            }
            if (dy == RD) {   // warps 8,9: uniform branch
                frs0 = fmaf(f4.x, f4.x, frs0);
                frs1 = fmaf(f4.y, f4.y, frs1);
                frs2 = fmaf(f4.z, f4.z, frs2);
                frs3 = fmaf(f4.w, f4.w, frs3);
            }

            float fv[4] = {f4.x, f4.y, f4.z, f4.w};
            float q[12] = {q0.x,q0.y,q0.z,q0.w, q1.x,q1.y,q1.z,q1.w, q2.x,q2.y,q2.z,q2.w};
            #pragma unroll
            for (int i = 0; i < 4; ++i) {
                #pragma unroll
                for (int dx = 0; dx < ND; ++dx) {
                    acc[i*ND + dx] = fmaf(fv[i], q[i + dx], acc[i*ND + dx]);
                }
            }
        }
        __syncthreads();
    }

    // exchange inverse norms through smem
    if (dy == RD) {
        float s[4] = {frs0, frs1, frs2, frs3};
        #pragma unroll
        for (int i = 0; i < 4; ++i)
            s_frn[ty * 32 + 4 * g + i] = 1.0f / fmaxf(sqrtf(s[i]), 1e-12f);
    }
    // every tid<576 owns halo position tid; tid<64 also owns tid+576
    s_fqn[tid] = 1.0f / fmaxf(sqrtf(fqs0), 1e-12f);
    if (tid < 64)
        s_fqn[p1] = 1.0f / fmaxf(sqrtf(fqs1), 1e-12f);
    __syncthreads();

    const int h = h0 + ty;
    const int w_base = w0 + 4 * g;

    float invfr[4];
    #pragma unroll
    for (int i = 0; i < 4; ++i)
        invfr[i] = s_frn[ty * 32 + 4 * g + i];

    float invq[12];
    #pragma unroll
    for (int j = 0; j < 12; ++j)
        invq[j] = s_fqn[(ty + dy) * 40 + 4 * g + j];

    const float scale = 1.0f / (float)CC;
    #pragma unroll
    for (int dx = 0; dx < ND; ++dx) {
        float4 o;
        o.x = acc[0*ND + dx] * invfr[0] * invq[0 + dx] * scale;
        o.y = acc[1*ND + dx] * invfr[1] * invq[1 + dx] * scale;
        o.z = acc[2*ND + dx] * invfr[2] * invq[2 + dx] * scale;
        o.w = acc[3*ND + dx] * invfr[3] * invq[3 + dx] * scale;
        size_t off = (((size_t)b * (ND*ND) + (size_t)(dy*ND + dx)) * HH + h) * WW + w_base;
        *(float4*)&out[off] = o;
    }
}

extern "C" void kernel_launch(void* const* d_in, const int* in_sizes, int n_in,
                              void* d_out, int out_size) {
    const float* fr = (const float*)d_in[0];
    const float* fq = (const float*)d_in[1];
    float* out = (float*)d_out;
    (void)in_sizes; (void)n_in; (void)out_size;

    cudaFuncSetAttribute(corr_kernel, cudaFuncAttributeMaxDynamicSharedMemorySize, SMEM_BYTES);

    dim3 grid(WW / TILE_W, HH / TILE_H, BB);   // (4, 12, 8)
    corr_kernel<<<grid, NTHREADS, SMEM_BYTES>>>(fr, fq, out);
}

// round 6
// speedup vs baseline: 2.7622x; 1.5612x over previous
#include <cuda_runtime.h>
#include <cstdint>
#include <math.h>

#define BB 8
#define CC 256
#define HH 96
#define WW 128
#define HWSZ (HH*WW)
#define RD 4
#define ND 9
#define TILE_H 8
#define TILE_W 32
#define NTHREADS 576
#define CHUNK 8
#define NCHUNK 32

#define FQ_STG 5120         // floats per fq buffer (8 ch * 16 * 40)
#define FR_STG 2048         // floats per fr buffer (8 ch * 8 * 32)
#define FQ_F (2*FQ_STG)
#define FR_F (2*FR_STG)
#define SMEM_FLOATS (FQ_F + FR_F + 256 + 640)
#define SMEM_BYTES  (SMEM_FLOATS * 4)

__device__ __forceinline__ void cpasync16(unsigned sa, const float* src) {
    asm volatile("cp.async.cg.shared.global [%0], [%1], 16;\n" :: "r"(sa), "l"(src));
}
__device__ __forceinline__ unsigned smem_u32(const void* p) {
    return (unsigned)__cvta_generic_to_shared(p);
}

#define STAGE(BUFBIT) do {                                                  \
    _Pragma("unroll")                                                       \
    for (int it = 0; it < 4; ++it) {                                        \
        if (val[it]) cpasync16(dst[it] + (BUFBIT) * dlt[it], src[it]);      \
        src[it] += (size_t)CHUNK * HWSZ;                                    \
    }                                                                       \
    asm volatile("cp.async.commit_group;\n");                               \
} while (0)

#define COMP(BUFBIT) do {                                                   \
    const float* sfqb_ = sm + (BUFBIT) * FQ_STG;                            \
    const float* sfrb_ = sm + FQ_F + (BUFBIT) * FR_STG;                     \
    _Pragma("unroll")                                                       \
    for (int ch = 0; ch < CHUNK; ++ch) {                                    \
        const float* fqc = sfqb_ + ch * 640;                                \
        const float* frc = sfrb_ + ch * 256;                                \
        float4 f4 = *(const float4*)(frc + ty * 32 + 4 * g);                \
        const float* rp = fqc + (ty + dy) * 40 + 4 * g;                     \
        float4 q0 = *(const float4*)(rp);                                   \
        float4 q1 = *(const float4*)(rp + 4);                               \
        float4 q2 = *(const float4*)(rp + 8);                               \
        float qv = fqc[tid];                                                \
        fqs0 = fmaf(qv, qv, fqs0);                                          \
        if (tid < 64) { float qv1 = fqc[tid + NTHREADS];                    \
                        fqs1 = fmaf(qv1, qv1, fqs1); }                      \
        if (dy == RD) {                                                     \
            frs0 = fmaf(f4.x, f4.x, frs0); frs1 = fmaf(f4.y, f4.y, frs1);   \
            frs2 = fmaf(f4.z, f4.z, frs2); frs3 = fmaf(f4.w, f4.w, frs3);   \
        }                                                                   \
        float fv[4] = {f4.x, f4.y, f4.z, f4.w};                             \
        float q[12] = {q0.x,q0.y,q0.z,q0.w, q1.x,q1.y,q1.z,q1.w,            \
                       q2.x,q2.y,q2.z,q2.w};                                \
        _Pragma("unroll")                                                   \
        for (int i = 0; i < 4; ++i)                                         \
            _Pragma("unroll")                                               \
            for (int dx = 0; dx < ND; ++dx)                                 \
                acc[i*ND + dx] = fmaf(fv[i], q[i + dx], acc[i*ND + dx]);    \
    }                                                                       \
} while (0)

__global__ __launch_bounds__(NTHREADS, 1)
void corr_kernel(const float* __restrict__ fr, const float* __restrict__ fq,
                 float* __restrict__ out) {
    extern __shared__ float sm[];
    float* s_fq  = sm;
    float* s_fr  = sm + FQ_F;
    float* s_frn = sm + FQ_F + FR_F;
    float* s_fqn = s_frn + 256;

    const int b  = blockIdx.z;
    const int h0 = blockIdx.y * TILE_H;
    const int w0 = blockIdx.x * TILE_W;
    const int tid = threadIdx.x;
    const int g  = tid & 7;
    const int ty = (tid >> 3) & 7;
    const int dy = tid >> 6;

    const float* frb = fr + (size_t)b * CC * HWSZ;
    const float* fqb = fq + (size_t)b * CC * HWSZ;

    // ---- precompute staging slots (fixed per thread across all chunks) ----
    const float* src[4];
    unsigned dst[4], dlt[4];
    bool val[4];
    #pragma unroll
    for (int it = 0; it < 4; ++it) {
        int idx = tid + it * NTHREADS;
        val[it] = false; src[it] = frb; dst[it] = smem_u32(sm); dlt[it] = 0;
        if (idx < 1280) {                       // fq halo tile slot
            int ch  = idx / 160;
            int rem = idx - ch * 160;
            int row = rem / 10;
            int c16 = rem - row * 10;
            int hg = h0 + row - RD;
            int wg = w0 + c16 * 4 - RD;
            bool v = (hg >= 0 && hg < HH && wg >= 0 && wg <= WW - 4);
            val[it] = v;
            dst[it] = smem_u32(s_fq + (ch * 16 + row) * 40 + c16 * 4);
            dlt[it] = FQ_STG * 4;
            if (v) src[it] = fqb + (size_t)ch * HWSZ + hg * WW + wg;
        } else if (idx < 1792) {                // fr tile slot
            int j   = idx - 1280;
            int ch  = j >> 6;
            int rem = j & 63;
            int row = rem >> 3;
            int c16 = rem & 7;
            val[it] = true;
            dst[it] = smem_u32(s_fr + (ch * 8 + row) * 32 + c16 * 4);
            dlt[it] = FR_STG * 4;
            src[it] = frb + (size_t)ch * HWSZ + (h0 + row) * WW + (w0 + c16 * 4);
        }
    }

    // zero fq buffers once (OOB halo slots are never overwritten by cp.async)
    for (int i = tid; i < FQ_F; i += NTHREADS) s_fq[i] = 0.f;
    // RACE FIX: all zero stores must complete before any thread's cp.async
    // can land in the same buffer.
    __syncthreads();

    float acc[36];
    #pragma unroll
    for (int i = 0; i < 36; ++i) acc[i] = 0.f;
    float frs0 = 0.f, frs1 = 0.f, frs2 = 0.f, frs3 = 0.f;
    float fqs0 = 0.f, fqs1 = 0.f;

    STAGE(0);   // chunk 0 -> buf0

    #pragma unroll 1
    for (int kk = 0; kk < NCHUNK / 2; ++kk) {
        // even chunk in buf0
        STAGE(1);                                     // chunk 2kk+1 -> buf1
        asm volatile("cp.async.wait_group 1;\n");
        __syncthreads();
        COMP(0);
        __syncthreads();
        // odd chunk in buf1
        if (kk < NCHUNK / 2 - 1) {
            STAGE(0);                                 // chunk 2kk+2 -> buf0
            asm volatile("cp.async.wait_group 1;\n");
        } else {
            asm volatile("cp.async.wait_group 0;\n");
        }
        __syncthreads();
        COMP(1);
        __syncthreads();
    }

    // ---- exchange inverse norms through smem ----
    if (dy == RD) {
        float s[4] = {frs0, frs1, frs2, frs3};
        #pragma unroll
        for (int i = 0; i < 4; ++i)
            s_frn[ty * 32 + 4 * g + i] = 1.0f / fmaxf(sqrtf(s[i]), 1e-12f);
    }
    s_fqn[tid] = 1.0f / fmaxf(sqrtf(fqs0), 1e-12f);
    if (tid < 64)
        s_fqn[tid + NTHREADS] = 1.0f / fmaxf(sqrtf(fqs1), 1e-12f);
    __syncthreads();

    const int h = h0 + ty;
    const int w_base = w0 + 4 * g;

    float invfr[4];
    #pragma unroll
    for (int i = 0; i < 4; ++i)
        invfr[i] = s_frn[ty * 32 + 4 * g + i];

    float invq[12];
    #pragma unroll
    for (int j = 0; j < 12; ++j)
        invq[j] = s_fqn[(ty + dy) * 40 + 4 * g + j];

    const float scale = 1.0f / (float)CC;
    #pragma unroll
    for (int dx = 0; dx < ND; ++dx) {
        float4 o;
        o.x = acc[0*ND + dx] * invfr[0] * invq[0 + dx] * scale;
        o.y = acc[1*ND + dx] * invfr[1] * invq[1 + dx] * scale;
        o.z = acc[2*ND + dx] * invfr[2] * invq[2 + dx] * scale;
        o.w = acc[3*ND + dx] * invfr[3] * invq[3 + dx] * scale;
        size_t off = (((size_t)b * (ND*ND) + (size_t)(dy*ND + dx)) * HH + h) * WW + w_base;
        *(float4*)&out[off] = o;
    }
}

extern "C" void kernel_launch(void* const* d_in, const int* in_sizes, int n_in,
                              void* d_out, int out_size) {
    const float* fr = (const float*)d_in[0];
    const float* fq = (const float*)d_in[1];
    float* out = (float*)d_out;
    (void)in_sizes; (void)n_in; (void)out_size;

    cudaFuncSetAttribute(corr_kernel, cudaFuncAttributeMaxDynamicSharedMemorySize, SMEM_BYTES);

    dim3 grid(WW / TILE_W, HH / TILE_H, BB);   // (4, 12, 8)
    corr_kernel<<<grid, NTHREADS, SMEM_BYTES>>>(fr, fq, out);
}